// round 1
// baseline (speedup 1.0000x reference)
#include <cuda_runtime.h>
#include <cuda_bf16.h>
#include <math.h>

// Problem constants
#define BQ   4096      // queries
#define NU   100000    // users
#define DIM  128
#define TOPK 5
#define K1   6         // TOPK+1
#define NSPLIT 10
#define NPS   (NU / NSPLIT)   // 10000 users per split
#define TM 64
#define TN 64
#define QBLKS (BQ / TM)       // 64

#define NEG_INF (-3.402823466e38f)

// ---------------- scratch (device globals: no runtime allocation) ----------
__device__ float g_ue_n[(size_t)NU * DIM];   // normalized user table (51.2 MB)
__device__ float g_q_n[(size_t)BQ * DIM];    // normalized queries
__device__ float g_cv[(size_t)BQ * NSPLIT * K1];
__device__ int   g_ci[(size_t)BQ * NSPLIT * K1];

// ---------------- Kernel A: L2 normalize (1 warp per row) ------------------
__global__ void norm_kernel(const float* __restrict__ q, const float* __restrict__ u) {
    int row  = blockIdx.x * (blockDim.x >> 5) + (threadIdx.x >> 5);
    int lane = threadIdx.x & 31;
    if (row >= NU + BQ) return;
    const float* src;
    float* dst;
    if (row < NU) { src = u + (size_t)row * DIM; dst = g_ue_n + (size_t)row * DIM; }
    else          { src = q + (size_t)(row - NU) * DIM; dst = g_q_n + (size_t)(row - NU) * DIM; }
    float4 v = *(const float4*)(src + lane * 4);
    float s = v.x * v.x + v.y * v.y + v.z * v.z + v.w * v.w;
    #pragma unroll
    for (int o = 16; o > 0; o >>= 1) s += __shfl_xor_sync(0xffffffffu, s, o);
    float nrm = sqrtf(s);
    float inv = 1.0f / fmaxf(nrm, 1e-12f);
    float4 o4 = make_float4(v.x * inv, v.y * inv, v.z * inv, v.w * inv);
    *(float4*)(dst + lane * 4) = o4;
}

// ---------------- Kernel B: fused sims GEMM + streaming top-6 --------------
// grid = (QBLKS, NSPLIT), block = 256 threads.
// smem: qs[128][64] (k-major), us[128][64] (k-major; reused as sims[64][64]),
//       per-query top-6 lists.
#define SMEM_B ((128 * TM + 128 * TN) * 4 + TM * K1 * 4 * 2 + TM * 4)

__global__ __launch_bounds__(256) void sim_topk_kernel() {
    extern __shared__ float sm[];
    float* qs  = sm;                    // 128*64
    float* us  = sm + 128 * TM;         // 128*64 ; reused as sims[64][64]
    float* lv  = us + 128 * TN;         // TM * K1
    int*   li  = (int*)(lv + TM * K1);  // TM * K1
    int*   lcnt = li + TM * K1;         // TM

    const int qb = blockIdx.x;
    const int sp = blockIdx.y;
    const int q0 = qb * TM;
    const int t  = threadIdx.x;

    // load q tile (k-major)
    for (int i = t; i < TM * (DIM / 4); i += 256) {
        int m = i / (DIM / 4), kg = i % (DIM / 4);
        float4 v = *(const float4*)(g_q_n + (size_t)(q0 + m) * DIM + kg * 4);
        qs[(kg * 4 + 0) * TM + m] = v.x;
        qs[(kg * 4 + 1) * TM + m] = v.y;
        qs[(kg * 4 + 2) * TM + m] = v.z;
        qs[(kg * 4 + 3) * TM + m] = v.w;
    }
    for (int i = t; i < TM; i += 256) lcnt[i] = 0;
    __syncthreads();

    const int u0 = sp * NPS;
    const int nblocks = (NPS + TN - 1) / TN;
    const int tx = t & 15, ty = t >> 4;
    const int m0 = ty * 4, n0 = tx * 4;
    const int w = t >> 5, lane = t & 31;

    for (int blk = 0; blk < nblocks; blk++) {
        const int ub = u0 + blk * TN;
        const int nvalid = min(TN, u0 + NPS - ub);

        // load u tile (k-major), zero-pad
        for (int i = t; i < TN * (DIM / 4); i += 256) {
            int n = i / (DIM / 4), kg = i % (DIM / 4);
            float4 v = make_float4(0.f, 0.f, 0.f, 0.f);
            if (n < nvalid) v = *(const float4*)(g_ue_n + (size_t)(ub + n) * DIM + kg * 4);
            us[(kg * 4 + 0) * TN + n] = v.x;
            us[(kg * 4 + 1) * TN + n] = v.y;
            us[(kg * 4 + 2) * TN + n] = v.z;
            us[(kg * 4 + 3) * TN + n] = v.w;
        }
        __syncthreads();

        // 4x4 register micro-tile, sequential k accumulation (fp32 FMA)
        float acc[4][4];
        #pragma unroll
        for (int i = 0; i < 4; i++)
            #pragma unroll
            for (int j = 0; j < 4; j++) acc[i][j] = 0.f;

        #pragma unroll 8
        for (int k = 0; k < DIM; k++) {
            float4 a = *(const float4*)(qs + k * TM + m0);
            float4 b = *(const float4*)(us + k * TN + n0);
            acc[0][0] = fmaf(a.x, b.x, acc[0][0]);
            acc[0][1] = fmaf(a.x, b.y, acc[0][1]);
            acc[0][2] = fmaf(a.x, b.z, acc[0][2]);
            acc[0][3] = fmaf(a.x, b.w, acc[0][3]);
            acc[1][0] = fmaf(a.y, b.x, acc[1][0]);
            acc[1][1] = fmaf(a.y, b.y, acc[1][1]);
            acc[1][2] = fmaf(a.y, b.z, acc[1][2]);
            acc[1][3] = fmaf(a.y, b.w, acc[1][3]);
            acc[2][0] = fmaf(a.z, b.x, acc[2][0]);
            acc[2][1] = fmaf(a.z, b.y, acc[2][1]);
            acc[2][2] = fmaf(a.z, b.z, acc[2][2]);
            acc[2][3] = fmaf(a.z, b.w, acc[2][3]);
            acc[3][0] = fmaf(a.w, b.x, acc[3][0]);
            acc[3][1] = fmaf(a.w, b.y, acc[3][1]);
            acc[3][2] = fmaf(a.w, b.z, acc[3][2]);
            acc[3][3] = fmaf(a.w, b.w, acc[3][3]);
        }
        __syncthreads();   // everyone done reading us -> safe to overwrite

        float* sims = us;  // reuse u-tile smem as the sims scratch
        #pragma unroll
        for (int i = 0; i < 4; i++)
            #pragma unroll
            for (int j = 0; j < 4; j++)
                sims[(m0 + i) * TN + (n0 + j)] = acc[i][j];
        __syncthreads();

        // streaming top-6: warp w owns queries [w*8, w*8+8)
        #pragma unroll 1
        for (int mm = 0; mm < TM / 8; mm++) {
            const int m = w * (TM / 8) + mm;
            float* lvr = lv + m * K1;
            int*   lir = li + m * K1;
            #pragma unroll 1
            for (int h = 0; h < 2; h++) {
                int col = h * 32 + lane;
                int cnt = lcnt[m];
                float thr = (cnt >= K1) ? lvr[K1 - 1] : NEG_INF;
                float v = sims[m * TN + col];
                bool cand = (col < nvalid) && (v > thr);
                unsigned mask = __ballot_sync(0xffffffffu, cand);
                if (lane == 0 && mask) {
                    int c = lcnt[m];
                    while (mask) {
                        int src = __ffs(mask) - 1;
                        mask &= mask - 1;
                        float vv = sims[m * TN + h * 32 + src];
                        int   uu = ub + h * 32 + src;
                        if (c >= K1 && !(vv > lvr[K1 - 1])) continue;
                        int j = (c < K1) ? c : K1 - 1;
                        while (j > 0 && vv > lvr[j - 1]) {  // strict: equal keeps lower index first
                            lvr[j] = lvr[j - 1];
                            lir[j] = lir[j - 1];
                            j--;
                        }
                        lvr[j] = vv;
                        lir[j] = uu;
                        if (c < K1) c++;
                    }
                    lcnt[m] = c;
                }
                __syncwarp();
            }
        }
        __syncthreads();
    }

    // emit per-split candidates
    for (int i = t; i < TM * K1; i += 256) {
        int m = i / K1, e = i % K1;
        int cnt = lcnt[m];
        float v  = (e < cnt) ? lv[i] : NEG_INF;
        int   id = (e < cnt) ? li[i] : 0x7fffffff;
        size_t o = ((size_t)(q0 + m) * NSPLIT + sp) * K1 + e;
        g_cv[o] = v;
        g_ci[o] = id;
    }
}

// ---------------- Kernel C: merge candidates + dup filter + gather ---------
__global__ void finalize_kernel(float* __restrict__ out) {
    __shared__ float cv[NSPLIT * K1];
    __shared__ int   ci[NSPLIT * K1];
    __shared__ int   sel[TOPK];
    __shared__ float selv[TOPK];

    const int q = blockIdx.x;
    const int t = threadIdx.x;
    if (t < NSPLIT * K1) {
        size_t o = (size_t)q * NSPLIT * K1 + t;
        cv[t] = g_cv[o];
        ci[t] = g_ci[o];
    }
    __syncthreads();

    if (t == 0) {
        // exact top-6 with jax top_k tie-break (value desc, index asc)
        float bv[K1];
        int   bi[K1];
        int cnt = 0;
        for (int i = 0; i < NSPLIT * K1; i++) {
            float v = cv[i];
            int  id = ci[i];
            bool better_than_last =
                (cnt < K1) || (v > bv[K1 - 1]) || (v == bv[K1 - 1] && id < bi[K1 - 1]);
            if (!better_than_last) continue;
            int p = (cnt < K1) ? cnt : K1 - 1;
            int j = p;
            while (j > 0 && (v > bv[j - 1] || (v == bv[j - 1] && id < bi[j - 1]))) {
                bv[j] = bv[j - 1];
                bi[j] = bi[j - 1];
                j--;
            }
            bv[j] = v;
            bi[j] = id;
            if (cnt < K1) cnt++;
        }
        // dup-threshold mask + stable valid-first ordering + pad-with-last
        int order[K1];
        int nv = 0;
        for (int i = 0; i < K1; i++) if (bv[i] < 0.9999f) order[nv++] = i;
        int oi = nv;
        for (int i = 0; i < K1; i++) if (!(bv[i] < 0.9999f)) order[oi++] = i;
        for (int j = 0; j < TOPK; j++) {
            int pos;
            if (nv > 0) pos = order[min(j, nv - 1)];
            else        pos = j;   // fallback: raw top-k
            sel[j]  = bi[pos];
            selv[j] = bv[pos];
        }
    }
    __syncthreads();

    float* oute = out;                                   // [BQ, TOPK, DIM]
    float* outs = out + (size_t)BQ * TOPK * DIM;         // [BQ, TOPK]
    #pragma unroll
    for (int j = 0; j < TOPK; j++) {
        oute[((size_t)q * TOPK + j) * DIM + t] = g_ue_n[(size_t)sel[j] * DIM + t];
    }
    if (t < TOPK) outs[(size_t)q * TOPK + t] = selv[t];
}

// ---------------- launch --------------------------------------------------
extern "C" void kernel_launch(void* const* d_in, const int* in_sizes, int n_in,
                              void* d_out, int out_size) {
    const float* q = (const float*)d_in[0];
    const float* u = (const float*)d_in[1];
    // defensive: identify which input is the 4096x128 query tensor
    if (n_in >= 2 && in_sizes[0] != BQ * DIM) {
        const float* tmp = q; q = u; u = tmp;
    }
    float* out = (float*)d_out;

    // A: normalize (1 warp/row, 8 rows per 256-thread block)
    int rows = NU + BQ;
    int blksA = (rows + 7) / 8;
    norm_kernel<<<blksA, 256>>>(q, u);

    // B: fused sims + streaming top-6 (67 KB dynamic smem -> opt in)
    cudaFuncSetAttribute(sim_topk_kernel,
                         cudaFuncAttributeMaxDynamicSharedMemorySize, SMEM_B);
    sim_topk_kernel<<<dim3(QBLKS, NSPLIT), 256, SMEM_B>>>();

    // C: merge + select + gather
    finalize_kernel<<<BQ, DIM>>>(out);
}

// round 3
// speedup vs baseline: 3.4950x; 3.4950x over previous
#include <cuda_runtime.h>
#include <cuda_bf16.h>
#include <math.h>
#include <cstdint>

// ---------------- problem constants ----------------
#define BQ   4096
#define NU   100000
#define DIM  128
#define TOPK 5
#define K1   6
#define NSPLIT 4
#define NPS   25000                    // users per split
#define TM 128                         // queries per CTA
#define TN 128                         // users per tile
#define QB (BQ / TM)                   // 32
#define NTILES ((NPS + TN - 1) / TN)   // 196 (last tile: 40 valid)
#define CAND 8
#define NCAND (NSPLIT * CAND)          // 32
#define SIMS_PITCH 132
#define NEG_INF (-3.402823466e38f)

// ---------------- device scratch -------------------------------------------
__device__ float         g_ue_n[(size_t)NU * DIM];
__device__ float         g_q_n[(size_t)BQ * DIM];
__device__ __nv_bfloat16 g_ub[(size_t)NU * DIM];
__device__ __nv_bfloat16 g_qb[(size_t)BQ * DIM];
__device__ int           g_ci[(size_t)BQ * NCAND];

// ---------------- helpers ---------------------------------------------------
static __device__ __forceinline__ uint32_t smem_u32(const void* p) {
    uint32_t a;
    asm("{ .reg .u64 t; cvta.to.shared.u64 t, %1; cvt.u32.u64 %0, t; }" : "=r"(a) : "l"(p));
    return a;
}
static __device__ __forceinline__ void cp_async16(uint32_t dst, const void* src, uint32_t srcbytes) {
    asm volatile("cp.async.cg.shared.global [%0], [%1], 16, %2;"
                 :: "r"(dst), "l"(src), "r"(srcbytes) : "memory");
}
static __device__ __forceinline__ void cp_commit() { asm volatile("cp.async.commit_group;" ::: "memory"); }
static __device__ __forceinline__ void cp_wait1()  { asm volatile("cp.async.wait_group 1;"  ::: "memory"); }

static __device__ __forceinline__ void ldsm_x4(uint32_t addr, uint32_t r[4]) {
    asm volatile("ldmatrix.sync.aligned.m8n8.x4.shared.b16 {%0,%1,%2,%3}, [%4];"
                 : "=r"(r[0]), "=r"(r[1]), "=r"(r[2]), "=r"(r[3]) : "r"(addr));
}
static __device__ __forceinline__ void mma_bf16(float c[4], const uint32_t a[4],
                                                uint32_t b0, uint32_t b1) {
    asm volatile("mma.sync.aligned.m16n8k16.row.col.f32.bf16.bf16.f32 "
                 "{%0,%1,%2,%3}, {%4,%5,%6,%7}, {%8,%9}, {%0,%1,%2,%3};"
                 : "+f"(c[0]), "+f"(c[1]), "+f"(c[2]), "+f"(c[3])
                 : "r"(a[0]), "r"(a[1]), "r"(a[2]), "r"(a[3]), "r"(b0), "r"(b1));
}

// swizzled byte offset inside a [128 rows x 256B] bf16 tile (16B chunks, XOR row)
static __device__ __forceinline__ uint32_t tile_off(int r, int chunk) {
    return (uint32_t)(r * 256 + ((chunk ^ (r & 7)) << 4));
}

// ---------------- Kernel A: normalize + bf16 convert ------------------------
__global__ void prep_kernel(const float* __restrict__ q, const float* __restrict__ u) {
    int row  = blockIdx.x * (blockDim.x >> 5) + (threadIdx.x >> 5);
    int lane = threadIdx.x & 31;
    if (row >= NU + BQ) return;
    const float* src; float* dstf; __nv_bfloat16* dstb;
    if (row < NU) { src = u + (size_t)row * DIM; dstf = g_ue_n + (size_t)row * DIM; dstb = g_ub + (size_t)row * DIM; }
    else { int r = row - NU; src = q + (size_t)r * DIM; dstf = g_q_n + (size_t)r * DIM; dstb = g_qb + (size_t)r * DIM; }
    float4 v = *(const float4*)(src + lane * 4);
    float s = v.x * v.x + v.y * v.y + v.z * v.z + v.w * v.w;
    #pragma unroll
    for (int o = 16; o > 0; o >>= 1) s += __shfl_xor_sync(0xffffffffu, s, o);
    float inv = 1.0f / fmaxf(sqrtf(s), 1e-12f);
    float4 o4 = make_float4(v.x * inv, v.y * inv, v.z * inv, v.w * inv);
    *(float4*)(dstf + lane * 4) = o4;
    __nv_bfloat162 b0 = __floats2bfloat162_rn(o4.x, o4.y);
    __nv_bfloat162 b1 = __floats2bfloat162_rn(o4.z, o4.w);
    uint2 pk = make_uint2(*(uint32_t*)&b0, *(uint32_t*)&b1);
    *(uint2*)(dstb + lane * 4) = pk;
}

// ---------------- Kernel B: HMMA bf16 sims + per-row streaming top-8 --------
// smem: A 32K | B0 32K | B1 32K | sims 128x132 f32 (67584B) | thr 512B | trig 512B
#define OFF_A    0
#define OFF_B0   32768
#define OFF_B1   65536
#define OFF_SIMS 98304
#define OFF_THR  (OFF_SIMS + SIMS_PITCH * TM * 4)   // 165888
#define OFF_TRIG (OFF_THR + 512)                    // 166400
#define SMEM_BYTES (OFF_TRIG + 512 + 1024)          // 167936

__global__ __launch_bounds__(256) void cand_kernel() {
    extern __shared__ char sraw[];
    uint32_t sb0 = smem_u32(sraw);
    uint32_t ab = (sb0 + 1023) & ~1023u;
    char* base = sraw + (ab - sb0);

    float* sims = (float*)(base + OFF_SIMS);
    float* thr  = (float*)(base + OFF_THR);
    int*   trig = (int*)(base + OFF_TRIG);

    const int t = threadIdx.x;
    const int w = t >> 5, lane = t & 31;
    const int wr = w >> 1, wc = w & 1;
    const int m0w = wr * 32;
    const int n0w = wc * 64;
    const int q0 = blockIdx.x * TM;
    const int u0 = blockIdx.y * NPS;

    // per-thread top-8 (owned by threads 0..127, row = t)
    float topv[CAND]; int topi[CAND];
    #pragma unroll
    for (int p = 0; p < CAND; p++) { topv[p] = NEG_INF; topi[p] = 0; }

    for (int i = t; i < TM; i += 256) { thr[i] = NEG_INF; trig[i] = 0; }

    // load query tile into swizzled smem
    {
        const uint4* src = (const uint4*)(g_qb + (size_t)q0 * DIM);
        for (int i = t; i < TM * 16; i += 256) {
            int r = i >> 4, c = i & 15;
            *(uint4*)(base + OFF_A + tile_off(r, c)) = src[i];
        }
    }
    __syncthreads();

    // hoist A fragments to registers (constant across all tiles)
    uint32_t afr[2][8][4];
    {
        uint32_t A_s = ab + OFF_A;
        #pragma unroll
        for (int mi = 0; mi < 2; mi++)
            #pragma unroll
            for (int k = 0; k < 8; k++) {
                int row = m0w + mi * 16 + (lane & 15);
                int ch  = 2 * k + (lane >> 4);
                ldsm_x4(A_s + tile_off(row, ch), afr[mi][k]);
            }
    }

    const uint32_t Bs_[2] = { ab + OFF_B0, ab + OFF_B1 };

    // B tile loader: thread t -> row t/2, 8 chunks
    auto issue_tile = [&](int tile, uint32_t Bs) {
        int r = t >> 1;
        int gidx = tile * TN + r;
        bool valid = gidx < NPS;
        const char* src = (const char*)(g_ub + (size_t)(u0 + (valid ? gidx : 0)) * DIM);
        uint32_t vb = valid ? 16u : 0u;
        int c0 = (t & 1) * 8;
        #pragma unroll
        for (int c = 0; c < 8; c++)
            cp_async16(Bs + tile_off(r, c0 + c), src + (size_t)(c0 + c) * 16, vb);
        cp_commit();
    };
    issue_tile(0, Bs_[0]);
    issue_tile(1, Bs_[1]);

    for (int i = 0; i < NTILES; i++) {
        const uint32_t Bs = Bs_[i & 1];
        cp_wait1();
        __syncthreads();

        // ---- MMA: warp tile 32 rows x 64 cols ----
        float acc[2][8][4];
        #pragma unroll
        for (int mi = 0; mi < 2; mi++)
            #pragma unroll
            for (int nf = 0; nf < 8; nf++)
                #pragma unroll
                for (int e = 0; e < 4; e++) acc[mi][nf][e] = 0.f;

        #pragma unroll
        for (int k = 0; k < 8; k++) {
            uint32_t bfr[4][4];
            #pragma unroll
            for (int nf4 = 0; nf4 < 4; nf4++) {
                int row = n0w + nf4 * 16 + (lane & 7) + ((lane >> 4) << 3);
                int ch  = 2 * k + ((lane >> 3) & 1);
                ldsm_x4(Bs + tile_off(row, ch), bfr[nf4]);
            }
            #pragma unroll
            for (int nf4 = 0; nf4 < 4; nf4++) {
                mma_bf16(acc[0][nf4 * 2 + 0], afr[0][k], bfr[nf4][0], bfr[nf4][1]);
                mma_bf16(acc[1][nf4 * 2 + 0], afr[1][k], bfr[nf4][0], bfr[nf4][1]);
                mma_bf16(acc[0][nf4 * 2 + 1], afr[0][k], bfr[nf4][2], bfr[nf4][3]);
                mma_bf16(acc[1][nf4 * 2 + 1], afr[1][k], bfr[nf4][2], bfr[nf4][3]);
            }
        }

        // ---- fast path: per-row max in registers, threshold test ----
        #pragma unroll
        for (int mi = 0; mi < 2; mi++)
            #pragma unroll
            for (int h = 0; h < 2; h++) {
                float mx = NEG_INF;
                #pragma unroll
                for (int nf = 0; nf < 8; nf++)
                    mx = fmaxf(mx, fmaxf(acc[mi][nf][2 * h], acc[mi][nf][2 * h + 1]));
                mx = fmaxf(mx, __shfl_xor_sync(0xffffffffu, mx, 1));
                mx = fmaxf(mx, __shfl_xor_sync(0xffffffffu, mx, 2));
                int row = m0w + mi * 16 + (lane >> 2) + h * 8;
                if ((lane & 3) == 0 && mx > thr[row]) trig[row] = 1;
            }
        __syncthreads();   // MMA + trig flags complete; B[s] consumed

        // ---- triggered warps spill accums to sims smem ----
        {
            int f = trig[m0w + lane];
            unsigned bal = __ballot_sync(0xffffffffu, f != 0);
            if (bal) {
                #pragma unroll
                for (int mi = 0; mi < 2; mi++) {
                    int row = m0w + mi * 16 + (lane >> 2);
                    #pragma unroll
                    for (int nf = 0; nf < 8; nf++) {
                        int col = n0w + nf * 8 + ((lane & 3) << 1);
                        *(float2*)&sims[row * SIMS_PITCH + col] =
                            make_float2(acc[mi][nf][0], acc[mi][nf][1]);
                        *(float2*)&sims[(row + 8) * SIMS_PITCH + col] =
                            make_float2(acc[mi][nf][2], acc[mi][nf][3]);
                    }
                }
            }
        }
        // prefetch tile i+2 into the buffer just consumed
        if (i + 2 < NTILES) issue_tile(i + 2, Bs);
        __syncthreads();

        // ---- owner threads scan triggered rows, update top-8 ----
        if (t < TM && trig[t]) {
            int nvalid = min(TN, NPS - i * TN);
            int cbase = u0 + i * TN;
            const float* srow = sims + t * SIMS_PITCH;
            for (int c = 0; c < nvalid; c++) {
                float v = srow[c];
                int idx = cbase + c;
                if (v > topv[CAND - 1] ||
                    (v == topv[CAND - 1] && idx < topi[CAND - 1])) {
                    // register swap-cascade insert, total order (v desc, idx asc)
                    #pragma unroll
                    for (int p = 0; p < CAND; p++) {
                        bool better = (v > topv[p]) || (v == topv[p] && idx < topi[p]);
                        if (better) {
                            float tv = topv[p]; topv[p] = v; v = tv;
                            int   ti = topi[p]; topi[p] = idx; idx = ti;
                        }
                    }
                }
            }
            thr[t] = topv[CAND - 1];
            trig[t] = 0;
        }
        __syncthreads();
    }

    // emit candidate indices
    if (t < TM) {
        size_t b = (size_t)(q0 + t) * NCAND + blockIdx.y * CAND;
        #pragma unroll
        for (int e = 0; e < CAND; e++) g_ci[b + e] = topi[e];
    }
}

// ---------------- Kernel C: exact rescore + select + gather -----------------
__global__ void finalize_kernel(float* __restrict__ out) {
    __shared__ float cv[NCAND];
    __shared__ int   ci[NCAND];
    __shared__ int   sel[TOPK];
    __shared__ float selv[TOPK];

    const int q = blockIdx.x;
    const int t = threadIdx.x;
    const int w = t >> 5, lane = t & 31;

    if (t < NCAND) ci[t] = g_ci[(size_t)q * NCAND + t];
    __syncthreads();

    // exact fp32 rescore: warp w handles candidates [w*8, w*8+8)
    float4 qv = *(const float4*)(g_q_n + (size_t)q * DIM + lane * 4);
    #pragma unroll 1
    for (int cc = 0; cc < 8; cc++) {
        int idx = ci[w * 8 + cc];
        float4 uv = *(const float4*)(g_ue_n + (size_t)idx * DIM + lane * 4);
        float s = qv.x * uv.x;
        s = fmaf(qv.y, uv.y, s);
        s = fmaf(qv.z, uv.z, s);
        s = fmaf(qv.w, uv.w, s);
        #pragma unroll
        for (int o = 16; o > 0; o >>= 1) s += __shfl_xor_sync(0xffffffffu, s, o);
        if (lane == 0) cv[w * 8 + cc] = s;
    }
    __syncthreads();

    if (t == 0) {
        float bv[K1]; int bi[K1]; int cnt = 0;
        for (int i = 0; i < NCAND; i++) {
            float v = cv[i]; int id = ci[i];
            bool better = (cnt < K1) || (v > bv[K1 - 1]) || (v == bv[K1 - 1] && id < bi[K1 - 1]);
            if (!better) continue;
            int j = (cnt < K1) ? cnt : K1 - 1;
            while (j > 0 && (v > bv[j - 1] || (v == bv[j - 1] && id < bi[j - 1]))) {
                bv[j] = bv[j - 1]; bi[j] = bi[j - 1]; j--;
            }
            bv[j] = v; bi[j] = id;
            if (cnt < K1) cnt++;
        }
        int order[K1]; int nv = 0;
        for (int i = 0; i < K1; i++) if (bv[i] < 0.9999f) order[nv++] = i;
        int oi = nv;
        for (int i = 0; i < K1; i++) if (!(bv[i] < 0.9999f)) order[oi++] = i;
        for (int j = 0; j < TOPK; j++) {
            int pos = (nv > 0) ? order[min(j, nv - 1)] : j;
            sel[j] = bi[pos]; selv[j] = bv[pos];
        }
    }
    __syncthreads();

    float* oute = out;                              // [BQ, TOPK, DIM]
    float* outs = out + (size_t)BQ * TOPK * DIM;    // [BQ, TOPK]
    #pragma unroll
    for (int j = 0; j < TOPK; j++)
        oute[((size_t)q * TOPK + j) * DIM + t] = g_ue_n[(size_t)sel[j] * DIM + t];
    if (t < TOPK) outs[(size_t)q * TOPK + t] = selv[t];
}

// ---------------- launch ----------------------------------------------------
extern "C" void kernel_launch(void* const* d_in, const int* in_sizes, int n_in,
                              void* d_out, int out_size) {
    const float* q = (const float*)d_in[0];
    const float* u = (const float*)d_in[1];
    if (n_in >= 2 && in_sizes[0] != BQ * DIM) { const float* tmp = q; q = u; u = tmp; }
    float* out = (float*)d_out;

    int rows = NU + BQ;
    prep_kernel<<<(rows + 7) / 8, 256>>>(q, u);

    cudaFuncSetAttribute(cand_kernel, cudaFuncAttributeMaxDynamicSharedMemorySize, SMEM_BYTES);
    cand_kernel<<<dim3(QB, NSPLIT), 256, SMEM_BYTES>>>();

    finalize_kernel<<<BQ, DIM>>>(out);
}

// round 4
// speedup vs baseline: 3.8305x; 1.0960x over previous
#include <cuda_runtime.h>
#include <cuda_bf16.h>
#include <cuda_fp16.h>
#include <math.h>
#include <cstdint>

// ---------------- problem constants ----------------
#define BQ   4096
#define NU   100000
#define DIM  128
#define TOPK 5
#define K1   6
#define NSPLIT 4
#define NPS   25000                    // users per split
#define TM 128                         // queries per CTA
#define TN 128                         // users per tile
#define QB (BQ / TM)                   // 32
#define NTILES ((NPS + TN - 1) / TN)   // 196 (last tile: 40 valid, 88 pad)
#define PADROWS (NTILES * TN - NPS)    // 88
#define CAND 8
#define NCAND (NSPLIT * CAND)          // 32
#define SP_U32 65                      // sims pitch in u32 (conflict-free scan)
#define NEG_INF (-3.402823466e38f)

// ---------------- device scratch -------------------------------------------
__device__ float    g_ue_n[(size_t)NU * DIM];                    // fp32 normalized users
__device__ float    g_q_n[(size_t)BQ * DIM];                     // fp32 normalized queries
__device__ uint32_t g_ubsw[(size_t)NSPLIT * NTILES * 8192];      // pre-swizzled f16 tiles
__device__ __half   g_qh[(size_t)BQ * DIM];                      // f16 queries (row-major)
__device__ int      g_ci[(size_t)BQ * NCAND];

// ---------------- helpers ---------------------------------------------------
static __device__ __forceinline__ uint32_t smem_u32(const void* p) {
    uint32_t a;
    asm("{ .reg .u64 t; cvta.to.shared.u64 t, %1; cvt.u32.u64 %0, t; }" : "=r"(a) : "l"(p));
    return a;
}
static __device__ __forceinline__ void ldsm_x4(uint32_t addr, uint32_t r[4]) {
    asm volatile("ldmatrix.sync.aligned.m8n8.x4.shared.b16 {%0,%1,%2,%3}, [%4];"
                 : "=r"(r[0]), "=r"(r[1]), "=r"(r[2]), "=r"(r[3]) : "r"(addr));
}
static __device__ __forceinline__ void mma_f16(uint32_t c[2], const uint32_t a[4],
                                               uint32_t b0, uint32_t b1) {
    asm volatile("mma.sync.aligned.m16n8k16.row.col.f16.f16.f16.f16 "
                 "{%0,%1}, {%2,%3,%4,%5}, {%6,%7}, {%0,%1};"
                 : "+r"(c[0]), "+r"(c[1])
                 : "r"(a[0]), "r"(a[1]), "r"(a[2]), "r"(a[3]), "r"(b0), "r"(b1));
}
static __device__ __forceinline__ void bulk_ld(uint32_t dst, const void* src,
                                               uint32_t bytes, uint32_t mbar) {
    asm volatile("cp.async.bulk.shared::cluster.global.mbarrier::complete_tx::bytes "
                 "[%0], [%1], %2, [%3];"
                 :: "r"(dst), "l"(src), "r"(bytes), "r"(mbar) : "memory");
}
#define MBARRIER_INIT(addr, cnt) \
    asm volatile("mbarrier.init.shared.b64 [%0], %1;" :: "r"((uint32_t)(addr)), "r"((uint32_t)(cnt)) : "memory")
#define MBARRIER_EXPECT_TX(addr, bytes) \
    asm volatile("mbarrier.arrive.expect_tx.shared.b64 _, [%0], %1;" :: "r"((uint32_t)(addr)), "r"((uint32_t)(bytes)) : "memory")
#define MBARRIER_WAIT_PARITY(mbar_addr, parity) do { \
    uint32_t _mbar = (uint32_t)(mbar_addr); \
    uint32_t _par = (uint32_t)(parity); \
    uint32_t _done; \
    asm volatile("{\n\t.reg .pred p;\n\t" \
        "mbarrier.try_wait.parity.acquire.cta.shared::cta.b64 p, [%1], %2;\n\t" \
        "selp.b32 %0, 1, 0, p;\n\t}" : "=r"(_done) : "r"(_mbar), "r"(_par) : "memory"); \
    if (!_done) { \
        asm volatile("{\n\t.reg .pred P1;\n\t" \
            "WAIT_LOOP_%=:\n\t" \
            "mbarrier.try_wait.parity.acquire.cta.shared::cta.b64 P1, [%0], %1, 0x989680;\n\t" \
            "@P1 bra.uni WAIT_DONE_%=;\n\t" \
            "bra.uni WAIT_LOOP_%=;\n\t" \
            "WAIT_DONE_%=:\n\t}" :: "r"(_mbar), "r"(_par) : "memory"); \
    } \
} while (0)
#define FENCE_PROXY_ASYNC() asm volatile("fence.proxy.async.shared::cta;" ::: "memory")

// swizzled byte offset inside a [128 rows x 256B] f16 tile (16B chunks, XOR by row)
static __device__ __forceinline__ uint32_t tile_off(int r, int chunk) {
    return (uint32_t)(r * 256 + ((chunk ^ (r & 7)) << 4));
}

// ---------------- Kernel A: normalize + f16 convert (+ pre-swizzle users) ---
__global__ void prep_kernel(const float* __restrict__ q, const float* __restrict__ u) {
    int row  = blockIdx.x * (blockDim.x >> 5) + (threadIdx.x >> 5);
    int lane = threadIdx.x & 31;
    int total = NU + BQ + NSPLIT * PADROWS;
    if (row >= total) return;

    if (row >= NU + BQ) {
        // zero a pad row of the swizzled table (last tile of each split)
        int pidx = row - (NU + BQ);
        int sp = pidx / PADROWS;
        int r  = (TN - PADROWS) + (pidx % PADROWS);     // rows 40..127 of tile 195
        size_t base = ((size_t)(sp * NTILES + (NTILES - 1))) << 13;   // u32 units
        uint32_t off = tile_off(r, lane >> 1) >> 2;                   // u32 index
        g_ubsw[base + off + (lane & 1) * 2]     = 0u;
        g_ubsw[base + off + (lane & 1) * 2 + 1] = 0u;
        return;
    }

    const float* src;
    if (row < NU) src = u + (size_t)row * DIM;
    else          src = q + (size_t)(row - NU) * DIM;
    float4 v = *(const float4*)(src + lane * 4);
    float s = v.x * v.x + v.y * v.y + v.z * v.z + v.w * v.w;
    #pragma unroll
    for (int o = 16; o > 0; o >>= 1) s += __shfl_xor_sync(0xffffffffu, s, o);
    float inv = 1.0f / fmaxf(sqrtf(s), 1e-12f);
    float4 o4 = make_float4(v.x * inv, v.y * inv, v.z * inv, v.w * inv);

    __half2 h0 = __floats2half2_rn(o4.x, o4.y);
    __half2 h1 = __floats2half2_rn(o4.z, o4.w);
    uint32_t p0 = *(uint32_t*)&h0, p1 = *(uint32_t*)&h1;

    if (row < NU) {
        *(float4*)(g_ue_n + (size_t)row * DIM + lane * 4) = o4;
        int sp = row / NPS, li = row % NPS;
        int tile = li >> 7, r = li & 127;
        size_t base = ((size_t)(sp * NTILES + tile)) << 13;       // u32 units
        uint32_t off = tile_off(r, lane >> 1) >> 2;               // 16B chunk -> u32 idx
        g_ubsw[base + off + (lane & 1) * 2]     = p0;
        g_ubsw[base + off + (lane & 1) * 2 + 1] = p1;
    } else {
        int r = row - NU;
        *(float4*)(g_q_n + (size_t)r * DIM + lane * 4) = o4;
        uint2 pk = make_uint2(p0, p1);
        *(uint2*)(g_qh + (size_t)r * DIM + lane * 4) = pk;
    }
}

// ---------------- Kernel B: f16 HMMA sims + spill/scan top-8 ----------------
// smem: A 32K | B0 32K | B1 32K | sims 128*65*4 | thr 512 | trig 512 | mbar 16
#define OFF_A    0
#define OFF_B0   32768
#define OFF_B1   65536
#define OFF_SIMS 98304
#define OFF_THR  (OFF_SIMS + 128 * SP_U32 * 4)     // 131584
#define OFF_TRIG (OFF_THR + 512)                   // 132096
#define OFF_MBAR (OFF_TRIG + 512)                  // 132608
#define SMEM_BYTES (OFF_MBAR + 64 + 1024)

__global__ __launch_bounds__(256) void cand_kernel() {
    extern __shared__ char sraw[];
    uint32_t sb0 = smem_u32(sraw);
    uint32_t ab = (sb0 + 1023) & ~1023u;
    char* base = sraw + (ab - sb0);

    uint32_t* simsu = (uint32_t*)(base + OFF_SIMS);
    float*    thr   = (float*)(base + OFF_THR);
    int*      trig  = (int*)(base + OFF_TRIG);
    const uint32_t MB = ab + OFF_MBAR;              // full[0]=MB, full[1]=MB+8

    const int t = threadIdx.x;
    const int w = t >> 5, lane = t & 31;
    const int wr = w >> 1, wc = w & 1;
    const int m0w = wr * 32;
    const int n0w = wc * 64;
    const int q0 = blockIdx.x * TM;
    const int sp = blockIdx.y;
    const int u0 = sp * NPS;

    float topv[CAND]; int topi[CAND];
    #pragma unroll
    for (int p = 0; p < CAND; p++) { topv[p] = NEG_INF; topi[p] = 0; }

    if (t == 0) { MBARRIER_INIT(MB, 1); MBARRIER_INIT(MB + 8, 1); }
    for (int i = t; i < TM; i += 256) { thr[i] = NEG_INF; trig[i] = 0; }

    // load query tile into swizzled smem (once)
    {
        const uint4* src = (const uint4*)(g_qh + (size_t)q0 * DIM);
        for (int i = t; i < TM * 16; i += 256) {
            int r = i >> 4, c = i & 15;
            *(uint4*)(base + OFF_A + tile_off(r, c)) = src[i];
        }
    }
    __syncthreads();
    FENCE_PROXY_ASYNC();

    const uint32_t Bs_[2] = { ab + OFF_B0, ab + OFF_B1 };
    const char* tb = (const char*)g_ubsw + ((size_t)sp * NTILES << 15);

    if (t == 0) {
        MBARRIER_EXPECT_TX(MB,     32768u); bulk_ld(Bs_[0], tb,           32768u, MB);
        MBARRIER_EXPECT_TX(MB + 8, 32768u); bulk_ld(Bs_[1], tb + 32768,   32768u, MB + 8);
    }

    // hoist A fragments (constant across tiles)
    uint32_t afr[2][8][4];
    {
        uint32_t A_s = ab + OFF_A;
        #pragma unroll
        for (int mi = 0; mi < 2; mi++)
            #pragma unroll
            for (int k = 0; k < 8; k++) {
                int row = m0w + mi * 16 + (lane & 15);
                int ch  = 2 * k + (lane >> 4);
                ldsm_x4(A_s + tile_off(row, ch), afr[mi][k]);
            }
    }

    int ph[2] = {0, 0};
    for (int i = 0; i < NTILES; i++) {
        const int s = i & 1;
        const uint32_t Bs = Bs_[s];
        MBARRIER_WAIT_PARITY(MB + s * 8, ph[s]); ph[s] ^= 1;

        // ---- MMA: warp tile 32 rows x 64 cols, f16 accum ----
        uint32_t acc[2][8][2];
        #pragma unroll
        for (int mi = 0; mi < 2; mi++)
            #pragma unroll
            for (int nf = 0; nf < 8; nf++) { acc[mi][nf][0] = 0u; acc[mi][nf][1] = 0u; }

        #pragma unroll
        for (int k = 0; k < 8; k++) {
            uint32_t bfr[4][4];
            #pragma unroll
            for (int nf4 = 0; nf4 < 4; nf4++) {
                int row = n0w + nf4 * 16 + (lane & 7) + ((lane >> 4) << 3);
                int ch  = 2 * k + ((lane >> 3) & 1);
                ldsm_x4(Bs + tile_off(row, ch), bfr[nf4]);
            }
            #pragma unroll
            for (int nf4 = 0; nf4 < 4; nf4++) {
                mma_f16(acc[0][nf4 * 2 + 0], afr[0][k], bfr[nf4][0], bfr[nf4][1]);
                mma_f16(acc[1][nf4 * 2 + 0], afr[1][k], bfr[nf4][0], bfr[nf4][1]);
                mma_f16(acc[0][nf4 * 2 + 1], afr[0][k], bfr[nf4][2], bfr[nf4][3]);
                mma_f16(acc[1][nf4 * 2 + 1], afr[1][k], bfr[nf4][2], bfr[nf4][3]);
            }
        }

        // ---- per-row max (packed) + threshold trig ----
        #pragma unroll
        for (int mi = 0; mi < 2; mi++)
            #pragma unroll
            for (int h = 0; h < 2; h++) {
                __half2 m2 = *(__half2*)&acc[mi][0][h];
                #pragma unroll
                for (int nf = 1; nf < 8; nf++)
                    m2 = __hmax2(m2, *(__half2*)&acc[mi][nf][h]);
                float mx = fmaxf(__low2float(m2), __high2float(m2));
                mx = fmaxf(mx, __shfl_xor_sync(0xffffffffu, mx, 1));
                mx = fmaxf(mx, __shfl_xor_sync(0xffffffffu, mx, 2));
                int row = m0w + mi * 16 + (lane >> 2) + h * 8;
                if ((lane & 3) == 0 && mx > thr[row]) trig[row] = 1;
            }
        __syncthreads();   // trig visible; all LDSMs of B[s] done

        // ---- spill triggered bands (packed f16x2) ----
        {
            int f = trig[m0w + lane];
            unsigned bal = __ballot_sync(0xffffffffu, f != 0);
            if (bal) {
                #pragma unroll
                for (int mi = 0; mi < 2; mi++) {
                    int row = m0w + mi * 16 + (lane >> 2);
                    #pragma unroll
                    for (int nf = 0; nf < 8; nf++) {
                        int cp = wc * 32 + nf * 4 + (lane & 3);
                        simsu[row * SP_U32 + cp]       = acc[mi][nf][0];
                        simsu[(row + 8) * SP_U32 + cp] = acc[mi][nf][1];
                    }
                }
            }
        }
        // refill B[s] with tile i+2 (B[s] fully consumed above)
        if (t == 0 && i + 2 < NTILES) {
            MBARRIER_EXPECT_TX(MB + s * 8, 32768u);
            bulk_ld(Bs, tb + ((size_t)(i + 2) << 15), 32768u, MB + s * 8);
        }
        __syncthreads();   // sims visible

        // ---- owner threads scan triggered rows ----
        if (t < TM && trig[t]) {
            int nvalid = min(TN, NPS - i * TN);
            int cbase = u0 + i * TN;
            const uint32_t* srow = simsu + t * SP_U32;
            for (int cp = 0; cp * 2 < nvalid; cp++) {
                uint32_t pk = srow[cp];
                __half2 hv = *(__half2*)&pk;
                #pragma unroll
                for (int hh = 0; hh < 2; hh++) {
                    int col = cp * 2 + hh;
                    if (col >= nvalid) break;
                    float v = hh ? __high2float(hv) : __low2float(hv);
                    int idx = cbase + col;
                    if (v > topv[CAND - 1] ||
                        (v == topv[CAND - 1] && idx < topi[CAND - 1])) {
                        float vv = v; int ii = idx;
                        #pragma unroll
                        for (int p = 0; p < CAND; p++) {
                            bool better = (vv > topv[p]) || (vv == topv[p] && ii < topi[p]);
                            if (better) {
                                float tv = topv[p]; topv[p] = vv; vv = tv;
                                int   ti = topi[p]; topi[p] = ii; ii = ti;
                            }
                        }
                    }
                }
            }
            thr[t] = topv[CAND - 1];
            trig[t] = 0;
        }
        __syncthreads();
    }

    if (t < TM) {
        size_t b = (size_t)(q0 + t) * NCAND + sp * CAND;
        #pragma unroll
        for (int e = 0; e < CAND; e++) g_ci[b + e] = topi[e];
    }
}

// ---------------- Kernel C: exact rescore + select + gather -----------------
__global__ void finalize_kernel(float* __restrict__ out) {
    __shared__ float cv[NCAND];
    __shared__ int   ci[NCAND];
    __shared__ int   sel[TOPK];
    __shared__ float selv[TOPK];

    const int q = blockIdx.x;
    const int t = threadIdx.x;
    const int w = t >> 5, lane = t & 31;

    if (t < NCAND) ci[t] = g_ci[(size_t)q * NCAND + t];
    __syncthreads();

    float4 qv = *(const float4*)(g_q_n + (size_t)q * DIM + lane * 4);
    #pragma unroll 1
    for (int cc = 0; cc < 8; cc++) {
        int idx = ci[w * 8 + cc];
        float4 uv = *(const float4*)(g_ue_n + (size_t)idx * DIM + lane * 4);
        float s = qv.x * uv.x;
        s = fmaf(qv.y, uv.y, s);
        s = fmaf(qv.z, uv.z, s);
        s = fmaf(qv.w, uv.w, s);
        #pragma unroll
        for (int o = 16; o > 0; o >>= 1) s += __shfl_xor_sync(0xffffffffu, s, o);
        if (lane == 0) cv[w * 8 + cc] = s;
    }
    __syncthreads();

    if (t == 0) {
        float bv[K1]; int bi[K1]; int cnt = 0;
        for (int i = 0; i < NCAND; i++) {
            float v = cv[i]; int id = ci[i];
            bool better = (cnt < K1) || (v > bv[K1 - 1]) || (v == bv[K1 - 1] && id < bi[K1 - 1]);
            if (!better) continue;
            int j = (cnt < K1) ? cnt : K1 - 1;
            while (j > 0 && (v > bv[j - 1] || (v == bv[j - 1] && id < bi[j - 1]))) {
                bv[j] = bv[j - 1]; bi[j] = bi[j - 1]; j--;
            }
            bv[j] = v; bi[j] = id;
            if (cnt < K1) cnt++;
        }
        int order[K1]; int nv = 0;
        for (int i = 0; i < K1; i++) if (bv[i] < 0.9999f) order[nv++] = i;
        int oi = nv;
        for (int i = 0; i < K1; i++) if (!(bv[i] < 0.9999f)) order[oi++] = i;
        for (int j = 0; j < TOPK; j++) {
            int pos = (nv > 0) ? order[min(j, nv - 1)] : j;
            sel[j] = bi[pos]; selv[j] = bv[pos];
        }
    }
    __syncthreads();

    float* oute = out;                              // [BQ, TOPK, DIM]
    float* outs = out + (size_t)BQ * TOPK * DIM;    // [BQ, TOPK]
    #pragma unroll
    for (int j = 0; j < TOPK; j++)
        oute[((size_t)q * TOPK + j) * DIM + t] = g_ue_n[(size_t)sel[j] * DIM + t];
    if (t < TOPK) outs[(size_t)q * TOPK + t] = selv[t];
}

// ---------------- launch ----------------------------------------------------
extern "C" void kernel_launch(void* const* d_in, const int* in_sizes, int n_in,
                              void* d_out, int out_size) {
    const float* q = (const float*)d_in[0];
    const float* u = (const float*)d_in[1];
    if (n_in >= 2 && in_sizes[0] != BQ * DIM) { const float* tmp = q; q = u; u = tmp; }
    float* out = (float*)d_out;

    int rows = NU + BQ + NSPLIT * PADROWS;
    prep_kernel<<<(rows + 7) / 8, 256>>>(q, u);

    cudaFuncSetAttribute(cand_kernel, cudaFuncAttributeMaxDynamicSharedMemorySize, SMEM_BYTES);
    cand_kernel<<<dim3(QB, NSPLIT), 256, SMEM_BYTES>>>();

    finalize_kernel<<<BQ, DIM>>>(out);
}